// round 6
// baseline (speedup 1.0000x reference)
#include <cuda_runtime.h>
#include <cuda_bf16.h>
#include <cstdint>

// LNSLinear == y = x @ W^T + bias (log-domain max/rescale is an exact identity).
// R5: single fused kernel. Each of 8 warps per CTA owns one K=64 slice and
// loads mma.sync fragments DIRECTLY from fp32 global (no SMEM staging, no
// cp.async, no ldmatrix, no mainloop syncthreads), converting to hi/lo bf16
// in registers. 3-product split (hi*hi + lo*hi + hi*lo), fp32 accum.
// One __syncthreads + 8-way SMEM reduce + bias at the end.

namespace {
constexpr int Ndim = 512, Kdim = 512;
constexpr int TM = 32, TN = 32;
constexpr int RSTRIDE = 33;              // padded SMEM row stride (floats)
constexpr int WTILE = 32 * RSTRIDE;      // floats per warp partial tile
}

__device__ __forceinline__ void mma16816(float* d, const uint32_t* a,
                                         const uint32_t* b) {
    asm volatile(
        "mma.sync.aligned.m16n8k16.row.col.f32.bf16.bf16.f32 "
        "{%0, %1, %2, %3}, {%4, %5, %6, %7}, {%8, %9}, {%0, %1, %2, %3};"
        : "+f"(d[0]), "+f"(d[1]), "+f"(d[2]), "+f"(d[3])
        : "r"(a[0]), "r"(a[1]), "r"(a[2]), "r"(a[3]), "r"(b[0]), "r"(b[1]));
}

// fp32 pair -> packed bf16x2 hi and lo (residual) planes.
__device__ __forceinline__ void cvt_hilo(float2 v, uint32_t& h, uint32_t& lo) {
    __nv_bfloat162 hh = __float22bfloat162_rn(v);
    const float2 hf = __bfloat1622float2(hh);
    __nv_bfloat162 ll = __float22bfloat162_rn(make_float2(v.x - hf.x, v.y - hf.y));
    h  = *reinterpret_cast<uint32_t*>(&hh);
    lo = *reinterpret_cast<uint32_t*>(&ll);
}

__global__ __launch_bounds__(256, 2) void lns_gemm_fused(
    const float* __restrict__ x, const float* __restrict__ w,
    const float* __restrict__ bias, float* __restrict__ out) {
    __shared__ float red[8 * WTILE];     // 8 x 32x32 partials, padded (~33.8KB)

    const int t   = threadIdx.x;
    const int wid = t >> 5;              // K-slice owner: K in [64*wid, 64*wid+64)
    const int l   = t & 31;
    const int g   = l >> 2;              // fragment group row 0..7
    const int t4  = l & 3;
    const int m0  = blockIdx.y * TM;
    const int n0  = blockIdx.x * TN;
    const int k0w = wid * 64;

    // Per-lane base row pointers (fragment addressing, PTX m16n8k16 layout).
    const float* a0 = x + (size_t)(m0 + g) * Kdim;        // A rows g / g+8 (+16 for mt=1)
    const float* b0 = w + (size_t)(n0 + g) * Kdim;        // B rows g (+8 per nt)

    float d[2][4][4];
#pragma unroll
    for (int i = 0; i < 2; ++i)
#pragma unroll
        for (int j = 0; j < 4; ++j)
#pragma unroll
            for (int q = 0; q < 4; ++q) d[i][j][q] = 0.0f;

#pragma unroll
    for (int ks = 0; ks < 4; ++ks) {
        const int c0 = k0w + ks * 16 + t4 * 2;            // lane k column

        // ---- gather fp32 fragments (all independent -> high MLP) ----
        float2 ap[2][4];                                  // [mt][a-reg]
#pragma unroll
        for (int mt = 0; mt < 2; ++mt) {
            const float* r0 = a0 + (size_t)(mt * 16) * Kdim;
            const float* r1 = r0 + 8 * Kdim;
            ap[mt][0] = *reinterpret_cast<const float2*>(r0 + c0);
            ap[mt][1] = *reinterpret_cast<const float2*>(r1 + c0);
            ap[mt][2] = *reinterpret_cast<const float2*>(r0 + c0 + 8);
            ap[mt][3] = *reinterpret_cast<const float2*>(r1 + c0 + 8);
        }
        float2 bp[4][2];                                  // [nt][b-reg]
#pragma unroll
        for (int nt = 0; nt < 4; ++nt) {
            const float* rn = b0 + (size_t)(nt * 8) * Kdim;
            bp[nt][0] = *reinterpret_cast<const float2*>(rn + c0);
            bp[nt][1] = *reinterpret_cast<const float2*>(rn + c0 + 8);
        }

        // ---- convert to hi/lo bf16 fragments ----
        uint32_t ah[2][4], al[2][4], bh[4][2], bl[4][2];
#pragma unroll
        for (int mt = 0; mt < 2; ++mt)
#pragma unroll
            for (int r = 0; r < 4; ++r) cvt_hilo(ap[mt][r], ah[mt][r], al[mt][r]);
#pragma unroll
        for (int nt = 0; nt < 4; ++nt)
#pragma unroll
            for (int r = 0; r < 2; ++r) cvt_hilo(bp[nt][r], bh[nt][r], bl[nt][r]);

        // ---- 3-product split MMA ----
#pragma unroll
        for (int mt = 0; mt < 2; ++mt)
#pragma unroll
            for (int nt = 0; nt < 4; ++nt) {
                mma16816(d[mt][nt], ah[mt], bh[nt]);      // hi*hi
                mma16816(d[mt][nt], al[mt], bh[nt]);      // lo*hi
                mma16816(d[mt][nt], ah[mt], bl[nt]);      // hi*lo
            }
    }

    // ---- store per-warp partial tile to SMEM ----
    float* rw = red + wid * WTILE;
#pragma unroll
    for (int mt = 0; mt < 2; ++mt)
#pragma unroll
        for (int nt = 0; nt < 4; ++nt) {
            const int r0 = mt * 16 + g;
            const int c  = nt * 8 + t4 * 2;
            rw[r0 * RSTRIDE + c]           = d[mt][nt][0];
            rw[r0 * RSTRIDE + c + 1]       = d[mt][nt][1];
            rw[(r0 + 8) * RSTRIDE + c]     = d[mt][nt][2];
            rw[(r0 + 8) * RSTRIDE + c + 1] = d[mt][nt][3];
        }
    __syncthreads();

    // ---- 8-way reduce + bias + store (thread t -> row t>>3, cols (t&7)*4) ----
    const int m  = t >> 3;
    const int nb = (t & 7) * 4;
    const float4 bv = *reinterpret_cast<const float4*>(bias + n0 + nb);
    float s0 = bv.x, s1 = bv.y, s2 = bv.z, s3 = bv.w;
#pragma unroll
    for (int ww = 0; ww < 8; ++ww) {
        const float* p = red + ww * WTILE + m * RSTRIDE + nb;
        s0 += p[0]; s1 += p[1]; s2 += p[2]; s3 += p[3];
    }
    float4 o; o.x = s0; o.y = s1; o.z = s2; o.w = s3;
    *reinterpret_cast<float4*>(out + (size_t)(m0 + m) * Ndim + n0 + nb) = o;
}

extern "C" void kernel_launch(void* const* d_in, const int* in_sizes, int n_in,
                              void* d_out, int out_size) {
    (void)in_sizes; (void)n_in; (void)out_size;
    const float* x    = (const float*)d_in[0];   // [512, 512]
    const float* w    = (const float*)d_in[1];   // [512, 512]
    const float* bias = (const float*)d_in[2];   // [512]
    float* out = (float*)d_out;                  // [512, 512] fp32

    dim3 grid(Ndim / TN, 512 / TM);              // 16 x 16 = 256 CTAs
    lns_gemm_fused<<<grid, 256>>>(x, w, bias, out);
}

// round 7
// speedup vs baseline: 1.1831x; 1.1831x over previous
#include <cuda_runtime.h>
#include <cuda_bf16.h>
#include <cstdint>

// LNSLinear == y = x @ W^T + bias (log-domain max/rescale is an exact identity).
// R6: ONE fused kernel. 128 CTAs of 64(M)x32(N), 8 warps (4x2, 16x16 warp
// tiles, full K per warp). Mainloop per K-chunk(64): coalesced fp32 LDG ->
// register hi/lo bf16 split -> swizzled STS planes -> ldmatrix -> 3-product
// mma.sync (hi*hi + lo*hi + hi*lo, fp32 accum). Double-buffered, 1 sync/chunk.
// No convert kernel, no scratch, no split-K reduce.

namespace {
constexpr int Ndim = 512, Kdim = 512;
constexpr int TM = 64, TN = 32, KC = 64;
constexpr int NCHUNK = Kdim / KC;          // 8
// Plane offsets inside one stage (bytes). Rows are 128B (64 bf16 = KC).
constexpr int OFF_AH = 0;                  // 64 rows
constexpr int OFF_AL = 8192;               // 64 rows
constexpr int OFF_BH = 16384;              // 32 rows
constexpr int OFF_BL = 20480;              // 32 rows
constexpr int STAGE  = 24576;              // 24 KB
}

__device__ __forceinline__ uint32_t smem_u32(const void* p) {
    uint32_t a;
    asm("{ .reg .u64 t; cvta.to.shared.u64 t, %1; cvt.u32.u64 %0, t; }"
        : "=r"(a) : "l"(p));
    return a;
}

__device__ __forceinline__ void ldm_x4(uint32_t* r, uint32_t addr) {
    asm volatile(
        "ldmatrix.sync.aligned.m8n8.x4.shared.b16 {%0, %1, %2, %3}, [%4];"
        : "=r"(r[0]), "=r"(r[1]), "=r"(r[2]), "=r"(r[3]) : "r"(addr));
}

__device__ __forceinline__ void mma16816(float* d, const uint32_t* a,
                                         const uint32_t* b) {
    asm volatile(
        "mma.sync.aligned.m16n8k16.row.col.f32.bf16.bf16.f32 "
        "{%0, %1, %2, %3}, {%4, %5, %6, %7}, {%8, %9}, {%0, %1, %2, %3};"
        : "+f"(d[0]), "+f"(d[1]), "+f"(d[2]), "+f"(d[3])
        : "r"(a[0]), "r"(a[1]), "r"(a[2]), "r"(a[3]), "r"(b[0]), "r"(b[1]));
}

// float4 -> hi bf16x2 pair + lo (residual) bf16x2 pair
__device__ __forceinline__ void cvt4(float4 v, uint2& h, uint2& lo) {
    __nv_bfloat162 h01 = __float22bfloat162_rn(make_float2(v.x, v.y));
    __nv_bfloat162 h23 = __float22bfloat162_rn(make_float2(v.z, v.w));
    const float2 f01 = __bfloat1622float2(h01);
    const float2 f23 = __bfloat1622float2(h23);
    __nv_bfloat162 l01 = __float22bfloat162_rn(make_float2(v.x - f01.x, v.y - f01.y));
    __nv_bfloat162 l23 = __float22bfloat162_rn(make_float2(v.z - f23.x, v.w - f23.y));
    h  = make_uint2(*reinterpret_cast<uint32_t*>(&h01),
                    *reinterpret_cast<uint32_t*>(&h23));
    lo = make_uint2(*reinterpret_cast<uint32_t*>(&l01),
                    *reinterpret_cast<uint32_t*>(&l23));
}

__global__ __launch_bounds__(256, 2) void lns_fused_gemm(
    const float* __restrict__ x, const float* __restrict__ w,
    const float* __restrict__ bias, float* __restrict__ out) {
    __shared__ char smem[2 * STAGE];       // 48 KB, double-buffered planes
    const uint32_t sb = smem_u32(smem);

    const int t   = threadIdx.x;
    const int wid = t >> 5;
    const int l   = t & 31;
    const int m0  = blockIdx.y * TM;
    const int n0  = blockIdx.x * TN;
    const int wm  = (wid & 3) * 16;        // warp m offset
    const int wn  = (wid >> 2) * 16;       // warp n offset

    // ---- loader mapping: 96 rows (64 A + 32 B) x 16 float4 cols; 6 per thread
    const float* lsrc[6];
    uint32_t ldh[6], ldl[6];               // byte offsets within stage (hi / lo)
#pragma unroll
    for (int i = 0; i < 6; ++i) {
        const int id  = t + 256 * i;
        const int row = id >> 4;           // 0..95
        const int q   = id & 15;           // float4 column
        const bool isA = row < 64;
        const int prow = isA ? row : row - 64;
        lsrc[i] = (isA ? x + (size_t)(m0 + row) * Kdim
                       : w + (size_t)(n0 + prow) * Kdim) + q * 4;
        const uint32_t boff =
            (uint32_t)(prow * 128 + ((q * 8) ^ ((prow & 7) * 16)));
        ldh[i] = (uint32_t)(isA ? OFF_AH : OFF_BH) + boff;
        ldl[i] = (uint32_t)(isA ? OFF_AL : OFF_BL) + boff;
    }

    // ---- ldmatrix lane addressing (validated R4 scheme) ----
    const int a_row = wm + (l & 15);
    const uint32_t a_rb = (uint32_t)(a_row * 128);
    const uint32_t a_xr = (uint32_t)((a_row & 7) * 16);
    const uint32_t a_c0 = (uint32_t)((l >> 4) * 16);
    const int b_row = wn + (l & 7) + ((l >> 4) << 3);
    const uint32_t b_rb = (uint32_t)(b_row * 128);
    const uint32_t b_xr = (uint32_t)((b_row & 7) * 16);
    const uint32_t b_c0 = (uint32_t)(((l >> 3) & 1) * 16);

    float d[2][4];
#pragma unroll
    for (int i = 0; i < 2; ++i)
#pragma unroll
        for (int j = 0; j < 4; ++j) d[i][j] = 0.0f;

    // ---- prologue: chunk 0 -> buffer 0 ----
    {
#pragma unroll
        for (int i = 0; i < 6; ++i) {
            const float4 v = *reinterpret_cast<const float4*>(lsrc[i]);
            uint2 h, lo; cvt4(v, h, lo);
            *reinterpret_cast<uint2*>(smem + ldh[i]) = h;
            *reinterpret_cast<uint2*>(smem + ldl[i]) = lo;
        }
    }
    __syncthreads();

    for (int c = 0; c < NCHUNK; ++c) {
        // issue next chunk's loads first (front-batched, latency hidden by MMA)
        float4 stg[6];
        if (c + 1 < NCHUNK) {
            const int kb = (c + 1) * KC;
#pragma unroll
            for (int i = 0; i < 6; ++i)
                stg[i] = *reinterpret_cast<const float4*>(lsrc[i] + kb);
        }

        // compute chunk c from buffer c&1
        const uint32_t s = sb + (uint32_t)(c & 1) * STAGE;
        const uint32_t ah_b = s + OFF_AH + a_rb;
        const uint32_t al_b = s + OFF_AL + a_rb;
        const uint32_t bh_b = s + OFF_BH + b_rb;
        const uint32_t bl_b = s + OFF_BL + b_rb;
#pragma unroll
        for (int ks = 0; ks < 4; ++ks) {
            const uint32_t cA = (uint32_t)(ks * 32) + a_c0;
            const uint32_t cB = (uint32_t)(ks * 32) + b_c0;
            uint32_t ah[4], al[4], bh[4], bl[4];
            ldm_x4(ah, ah_b + (cA ^ a_xr));
            ldm_x4(al, al_b + (cA ^ a_xr));
            ldm_x4(bh, bh_b + (cB ^ b_xr));
            ldm_x4(bl, bl_b + (cB ^ b_xr));
#pragma unroll
            for (int nt = 0; nt < 2; ++nt) {
                mma16816(d[nt], ah, bh + 2 * nt);   // hi*hi
                mma16816(d[nt], al, bh + 2 * nt);   // lo*hi
                mma16816(d[nt], ah, bl + 2 * nt);   // hi*lo
            }
        }

        // convert + store next chunk into the other buffer
        if (c + 1 < NCHUNK) {
            char* sn = smem + ((c + 1) & 1) * STAGE;
#pragma unroll
            for (int i = 0; i < 6; ++i) {
                uint2 h, lo; cvt4(stg[i], h, lo);
                *reinterpret_cast<uint2*>(sn + ldh[i]) = h;
                *reinterpret_cast<uint2*>(sn + ldl[i]) = lo;
            }
        }
        __syncthreads();
    }

    // ---- epilogue: direct store with bias (full-K warps, no reduce) ----
    const int g  = l >> 2;
    const int t4 = l & 3;
    const int row0 = m0 + wm + g;
#pragma unroll
    for (int nt = 0; nt < 2; ++nt) {
        const int col = n0 + wn + nt * 8 + t4 * 2;
        const float2 bv = *reinterpret_cast<const float2*>(bias + col);
        float2 o0, o1;
        o0.x = d[nt][0] + bv.x;  o0.y = d[nt][1] + bv.y;
        o1.x = d[nt][2] + bv.x;  o1.y = d[nt][3] + bv.y;
        *reinterpret_cast<float2*>(out + (size_t)row0 * Ndim + col) = o0;
        *reinterpret_cast<float2*>(out + (size_t)(row0 + 8) * Ndim + col) = o1;
    }
}

extern "C" void kernel_launch(void* const* d_in, const int* in_sizes, int n_in,
                              void* d_out, int out_size) {
    (void)in_sizes; (void)n_in; (void)out_size;
    const float* x    = (const float*)d_in[0];   // [512, 512]
    const float* w    = (const float*)d_in[1];   // [512, 512]
    const float* bias = (const float*)d_in[2];   // [512]
    float* out = (float*)d_out;                  // [512, 512] fp32

    dim3 grid(Ndim / TN, 512 / TM);              // 16 x 8 = 128 CTAs, one wave
    lns_fused_gemm<<<grid, 256>>>(x, w, bias, out);
}

// round 8
// speedup vs baseline: 1.4588x; 1.2330x over previous
#include <cuda_runtime.h>
#include <cuda_fp16.h>
#include <cstdint>

// LNSLinear == y = x @ W^T + bias (log-domain max/rescale is an exact identity).
// R7: single-product fp16 HMMA (fp16 x fp16 products are EXACT in fp32; only
// input rounding contributes: predicted norm rel_err ~4e-4 < 1e-3 gate,
// calibrated against R3-R6 where bf16-3-product predicted 3.8e-6 vs 4.5e-6
// measured). Structure: 256 CTAs (32x32 tile), 128 threads; warp s privately
// owns K-slice [128s,128s+128): LDG fp32 -> cvt fp16 -> private SMEM plane ->
// ldmatrix -> 8 ks x 8 mma. NO __syncthreads until the 4-way epilogue reduce;
// warps fully decoupled (attacks the measured lockstep/latency limiter).

namespace {
constexpr int Ndim = 512, Kdim = 512;
constexpr int SMEM_BYTES = 65536;      // A planes 4x8KB @0, B planes 4x8KB @32KB
}

__device__ __forceinline__ uint32_t smem_u32(const void* p) {
    uint32_t a;
    asm("{ .reg .u64 t; cvta.to.shared.u64 t, %1; cvt.u32.u64 %0, t; }"
        : "=r"(a) : "l"(p));
    return a;
}

__device__ __forceinline__ void ldm_x4(uint32_t* r, uint32_t addr) {
    asm volatile(
        "ldmatrix.sync.aligned.m8n8.x4.shared.b16 {%0, %1, %2, %3}, [%4];"
        : "=r"(r[0]), "=r"(r[1]), "=r"(r[2]), "=r"(r[3]) : "r"(addr));
}

__device__ __forceinline__ void mma16816(float* d, const uint32_t* a,
                                         const uint32_t* b) {
    asm volatile(
        "mma.sync.aligned.m16n8k16.row.col.f32.f16.f16.f32 "
        "{%0, %1, %2, %3}, {%4, %5, %6, %7}, {%8, %9}, {%0, %1, %2, %3};"
        : "+f"(d[0]), "+f"(d[1]), "+f"(d[2]), "+f"(d[3])
        : "r"(a[0]), "r"(a[1]), "r"(a[2]), "r"(a[3]), "r"(b[0]), "r"(b[1]));
}

// float4 -> 4 packed fp16 (8 bytes)
__device__ __forceinline__ uint2 cvt_h4(float4 v) {
    __half2 h01 = __float22half2_rn(make_float2(v.x, v.y));
    __half2 h23 = __float22half2_rn(make_float2(v.z, v.w));
    return make_uint2(*reinterpret_cast<uint32_t*>(&h01),
                      *reinterpret_cast<uint32_t*>(&h23));
}

__global__ __launch_bounds__(128, 2) void lns_fp16_gemm(
    const float* __restrict__ x, const float* __restrict__ w,
    const float* __restrict__ bias, float* __restrict__ out) {
    extern __shared__ char sm[];
    const uint32_t sb = smem_u32(sm);

    const int t  = threadIdx.x;
    const int wd = t >> 5;             // warp = K-slice owner
    const int l  = t & 31;
    const int m0 = blockIdx.y * 32;
    const int n0 = blockIdx.x * 32;

    // ---- loader: thread t owns float4 column t across all 64 rows (A+B).
    // Its 4 fp32 -> 8B fp16 chunk c8 = t&31 of plane t>>5 (k = (t&31)*4 + plane*128).
    const int c8  = t & 31;
    const uint32_t q16 = (uint32_t)(c8 >> 1);
    const uint32_t lo8 = (uint32_t)((c8 & 1) * 8);
    char* const plA = sm + (t >> 5) * 8192;
    char* const plB = sm + 32768 + (t >> 5) * 8192;
    const float* xs = x + (size_t)m0 * Kdim + t * 4;
    const float* ws = w + (size_t)n0 * Kdim + t * 4;

#pragma unroll
    for (int jb = 0; jb < 4; ++jb) {
        float4 va[8], vb[8];
#pragma unroll
        for (int j = 0; j < 8; ++j) {
            va[j] = *reinterpret_cast<const float4*>(xs + (size_t)(jb * 8 + j) * Kdim);
            vb[j] = *reinterpret_cast<const float4*>(ws + (size_t)(jb * 8 + j) * Kdim);
        }
#pragma unroll
        for (int j = 0; j < 8; ++j) {
            const int r = jb * 8 + j;
            const uint32_t off =
                (uint32_t)(r * 256) + (((q16 ^ (uint32_t)(r & 7)) << 4) + lo8);
            *reinterpret_cast<uint2*>(plA + off) = cvt_h4(va[j]);
            *reinterpret_cast<uint2*>(plB + off) = cvt_h4(vb[j]);
        }
    }
    __syncwarp();   // warp s reads ONLY its own plane (written by itself)

    // ---- compute: warp wd, slice planes (256B rows, xor-swizzled 16B chunks)
    const uint32_t paA = sb + wd * 8192;
    const uint32_t paB = sb + 32768 + wd * 8192;
    const int rA   = l & 15;              // + mt*16
    const int selA = l >> 4;              // 16B chunk within k16
    const int rB   = (l & 7) + ((l >> 4) << 3);   // + g*16
    const int selB = (l >> 3) & 1;

    float d[2][4][4];
#pragma unroll
    for (int i = 0; i < 2; ++i)
#pragma unroll
        for (int j = 0; j < 4; ++j)
#pragma unroll
            for (int e = 0; e < 4; ++e) d[i][j][e] = 0.0f;

#pragma unroll
    for (int ks = 0; ks < 8; ++ks) {
        uint32_t af[2][4], bf[2][4];
#pragma unroll
        for (int mt = 0; mt < 2; ++mt) {
            const int row = mt * 16 + rA;
            const uint32_t q = (uint32_t)(2 * ks + selA);
            ldm_x4(af[mt], paA + row * 256 + ((q ^ (uint32_t)(row & 7)) << 4));
        }
#pragma unroll
        for (int g = 0; g < 2; ++g) {
            const int row = g * 16 + rB;
            const uint32_t q = (uint32_t)(2 * ks + selB);
            ldm_x4(bf[g], paB + row * 256 + ((q ^ (uint32_t)(row & 7)) << 4));
        }
#pragma unroll
        for (int mt = 0; mt < 2; ++mt)
#pragma unroll
            for (int ng = 0; ng < 4; ++ng)
                mma16816(d[mt][ng], af[mt], bf[ng >> 1] + (ng & 1) * 2);
    }

    // ---- epilogue: 4-way K-slice reduce in SMEM (planes reused), + bias ----
    __syncthreads();
    float* red = reinterpret_cast<float*>(sm) + wd * 1024;   // [32][32]
    const int gr = l >> 2;
    const int t4 = l & 3;
#pragma unroll
    for (int mt = 0; mt < 2; ++mt)
#pragma unroll
        for (int ng = 0; ng < 4; ++ng) {
            const int r = mt * 16 + gr;
            const int c = ng * 8 + t4 * 2;
            red[r * 32 + c]           = d[mt][ng][0];
            red[r * 32 + c + 1]       = d[mt][ng][1];
            red[(r + 8) * 32 + c]     = d[mt][ng][2];
            red[(r + 8) * 32 + c + 1] = d[mt][ng][3];
        }
    __syncthreads();

    const float* rb = reinterpret_cast<const float*>(sm);
#pragma unroll
    for (int e = 0; e < 2; ++e) {
        const int i  = t * 2 + e;          // 0..255 float4 ids over 32x32
        const int r  = i >> 3;
        const int c  = (i & 7) * 4;
        const float4 bv = *reinterpret_cast<const float4*>(bias + n0 + c);
        float s0 = bv.x, s1 = bv.y, s2 = bv.z, s3 = bv.w;
#pragma unroll
        for (int s = 0; s < 4; ++s) {
            const float* p = rb + s * 1024 + r * 32 + c;
            s0 += p[0]; s1 += p[1]; s2 += p[2]; s3 += p[3];
        }
        float4 o; o.x = s0; o.y = s1; o.z = s2; o.w = s3;
        *reinterpret_cast<float4*>(out + (size_t)(m0 + r) * Ndim + n0 + c) = o;
    }
}

extern "C" void kernel_launch(void* const* d_in, const int* in_sizes, int n_in,
                              void* d_out, int out_size) {
    (void)in_sizes; (void)n_in; (void)out_size;
    const float* x    = (const float*)d_in[0];   // [512, 512]
    const float* w    = (const float*)d_in[1];   // [512, 512]
    const float* bias = (const float*)d_in[2];   // [512]
    float* out = (float*)d_out;                  // [512, 512] fp32

    static bool attr_set = false;
    if (!attr_set) {
        cudaFuncSetAttribute(lns_fp16_gemm,
                             cudaFuncAttributeMaxDynamicSharedMemorySize,
                             SMEM_BYTES);
        attr_set = true;
    }
    dim3 grid(Ndim / 32, 512 / 32);              // 16 x 16 = 256 CTAs, one wave
    lns_fp16_gemm<<<grid, 128, SMEM_BYTES>>>(x, w, bias, out);
}